// round 6
// baseline (speedup 1.0000x reference)
#include <cuda_runtime.h>

#define NFFT 1024
#define NT   128
#define WARPS (NT / 32)

// exp(+2*pi*i*k/32), k = 0..15  (inverse-FFT sign)
__device__ const float TW32R[16] = {
    1.00000000f,  0.98078528f,  0.92387953f,  0.83146961f,
    0.70710678f,  0.55557023f,  0.38268343f,  0.19509032f,
    0.00000000f, -0.19509032f, -0.38268343f, -0.55557023f,
   -0.70710678f, -0.83146961f, -0.92387953f, -0.98078528f
};
__device__ const float TW32I[16] = {
    0.00000000f,  0.19509032f,  0.38268343f,  0.55557023f,
    0.70710678f,  0.83146961f,  0.92387953f,  0.98078528f,
    1.00000000f,  0.98078528f,  0.92387953f,  0.83146961f,
    0.70710678f,  0.55557023f,  0.38268343f,  0.19509032f
};

// In-register 32-point inverse DFT (unnormalized), natural in -> natural out.
__device__ __forceinline__ void fft32_reg(float vr[32], float vi[32])
{
    // bit-reversal (rev5) permutation — register renaming, free
    #pragma unroll
    for (int i = 0; i < 32; i++) {
        int j = ((i & 1) << 4) | ((i & 2) << 2) | (i & 4) | ((i & 8) >> 2) | ((i & 16) >> 4);
        if (j > i) {
            float tr = vr[i]; vr[i] = vr[j]; vr[j] = tr;
            float ti = vi[i]; vi[i] = vi[j]; vi[j] = ti;
        }
    }
    #pragma unroll
    for (int h = 1; h < 32; h <<= 1) {
        #pragma unroll
        for (int g = 0; g < 32; g += 2 * h) {
            #pragma unroll
            for (int j = 0; j < h; j++) {
                const float wr = TW32R[j * (16 / h)];
                const float wi = TW32I[j * (16 / h)];
                const int a = g + j, b = g + j + h;
                float tr = vr[b] * wr - vi[b] * wi;
                float ti = vr[b] * wi + vi[b] * wr;
                vr[b] = vr[a] - tr;  vi[b] = vi[a] - ti;
                vr[a] = vr[a] + tr;  vi[a] = vi[a] + ti;
            }
        }
    }
}

// One warp per 1024-pt inverse FFT: 1024 = 32 x 32 Cooley-Tukey.
// __launch_bounds__(128, 5): regs capped ~102 -> 20 warps/SM (accept small spill).
__global__ __launch_bounds__(NT, 5) void ifft1024_warp(
    const float* __restrict__ re,
    const float* __restrict__ im,
    float* __restrict__ out_r,
    float* __restrict__ out_i)
{
    __shared__ float tbuf[WARPS][1024];   // 4KB per warp

    const int lane = threadIdx.x & 31;
    const int w    = threadIdx.x >> 5;
    const long long row = (long long)blockIdx.x * WARPS + w;

    const float* xr = re + row * NFFT;
    const float* xi = im + row * NFFT;

    float vr[32], vi[32];

    // Coalesced loads: lanes stride-1, 32 rows apart per register slot.
    #pragma unroll
    for (int n2 = 0; n2 < 32; n2++) {
        vr[n2] = xr[lane + 32 * n2];
        vi[n2] = xi[lane + 32 * n2];
    }

    // Step 1: A[lane, k2] = sum_{n2} W32^{n2 k2} x[lane + 32 n2]
    fft32_reg(vr, vi);

    // Step 2: multiply by inv * W1024^{lane * k2}, inv = 1/1024 folded in
    // (every output element passes here exactly once -> global IFFT scale).
    // 4 parallel chains of 8 dependent cmuls (serial depth /4 vs one chain).
    {
        const float inv = 1.0f / (float)NFFT;
        float s1, c1, s8, c8, s16, c16;
        sincospif((float)lane * (1.0f / 512.0f), &s1, &c1);    // w^1
        sincospif((float)lane * (1.0f / 64.0f),  &s8, &c8);    // w^8
        sincospif((float)lane * (1.0f / 32.0f),  &s16, &c16);  // w^16
        float c24 = c16 * c8 - s16 * s8;                       // w^24
        float s24 = c16 * s8 + s16 * c8;

        float cwr[4], cwi[4];
        cwr[0] = inv;        cwi[0] = 0.0f;
        cwr[1] = inv * c8;   cwi[1] = inv * s8;
        cwr[2] = inv * c16;  cwi[2] = inv * s16;
        cwr[3] = inv * c24;  cwi[3] = inv * s24;

        #pragma unroll
        for (int j = 0; j < 8; j++) {
            #pragma unroll
            for (int q = 0; q < 4; q++) {
                const int k = 8 * q + j;
                float br = vr[k] * cwr[q] - vi[k] * cwi[q];
                float bi = vr[k] * cwi[q] + vi[k] * cwr[q];
                vr[k] = br;  vi[k] = bi;
                float nr = cwr[q] * c1 - cwi[q] * s1;
                cwi[q]   = cwr[q] * s1 + cwi[q] * c1;
                cwr[q]   = nr;
            }
        }
    }

    // 32x32 transpose through warp-private shared, XOR-swizzled (conflict-free).
    float* buf = tbuf[w];
    #pragma unroll
    for (int k2 = 0; k2 < 32; k2++) buf[lane * 32 + (k2 ^ lane)] = vr[k2];
    __syncwarp();
    #pragma unroll
    for (int n1 = 0; n1 < 32; n1++) vr[n1] = buf[n1 * 32 + (lane ^ n1)];
    __syncwarp();
    #pragma unroll
    for (int k2 = 0; k2 < 32; k2++) buf[lane * 32 + (k2 ^ lane)] = vi[k2];
    __syncwarp();
    #pragma unroll
    for (int n1 = 0; n1 < 32; n1++) vi[n1] = buf[n1 * 32 + (lane ^ n1)];

    // Step 3: X[lane + 32 k1] = sum_{n1} W32^{n1 k1} B[n1, lane]
    fft32_reg(vr, vi);

    // Coalesced stores (scale already applied in step 2).
    float* orow  = out_r + row * NFFT;
    float* oirow = out_i + row * NFFT;
    #pragma unroll
    for (int k1 = 0; k1 < 32; k1++) {
        orow[lane + 32 * k1]  = vr[k1];
        oirow[lane + 32 * k1] = vi[k1];
    }
}

extern "C" void kernel_launch(void* const* d_in, const int* in_sizes, int n_in,
                              void* d_out, int out_size)
{
    const float* re = (const float*)d_in[0];
    const float* im = (const float*)d_in[1];
    float* out = (float*)d_out;

    const long long n_elems = (long long)in_sizes[0];   // 8*4096*1024
    const int nrows = (int)(n_elems / NFFT);            // 32768

    float* out_r = out;
    float* out_i = out + n_elems;                       // [yr | yi]

    ifft1024_warp<<<nrows / WARPS, NT>>>(re, im, out_r, out_i);
}

// round 7
// speedup vs baseline: 1.0998x; 1.0998x over previous
#include <cuda_runtime.h>

#define NFFT 1024
#define NT   256
#define WARPS (NT / 32)

// In-register 32-point inverse DFT (unnormalized), natural in -> natural out.
// constexpr twiddles => guaranteed immediate folding (FFMA-imm, trivial stages
// become pure add/sub), zero memory traffic for twiddles.
__device__ __forceinline__ void fft32_reg(float vr[32], float vi[32])
{
    // exp(+2*pi*i*k/32), k = 0..15  (inverse-FFT sign)
    constexpr float TR[16] = {
        1.00000000f,  0.98078528f,  0.92387953f,  0.83146961f,
        0.70710678f,  0.55557023f,  0.38268343f,  0.19509032f,
        0.00000000f, -0.19509032f, -0.38268343f, -0.55557023f,
       -0.70710678f, -0.83146961f, -0.92387953f, -0.98078528f
    };
    constexpr float TI[16] = {
        0.00000000f,  0.19509032f,  0.38268343f,  0.55557023f,
        0.70710678f,  0.83146961f,  0.92387953f,  0.98078528f,
        1.00000000f,  0.98078528f,  0.92387953f,  0.83146961f,
        0.70710678f,  0.55557023f,  0.38268343f,  0.19509032f
    };

    // bit-reversal (rev5) permutation — register renaming, free
    #pragma unroll
    for (int i = 0; i < 32; i++) {
        int j = ((i & 1) << 4) | ((i & 2) << 2) | (i & 4) | ((i & 8) >> 2) | ((i & 16) >> 4);
        if (j > i) {
            float tr = vr[i]; vr[i] = vr[j]; vr[j] = tr;
            float ti = vi[i]; vi[i] = vi[j]; vi[j] = ti;
        }
    }
    #pragma unroll
    for (int h = 1; h < 32; h <<= 1) {
        #pragma unroll
        for (int g = 0; g < 32; g += 2 * h) {
            #pragma unroll
            for (int j = 0; j < h; j++) {
                constexpr int dummy = 0; (void)dummy;
                const float wr = TR[j * (16 / h)];
                const float wi = TI[j * (16 / h)];
                const int a = g + j, b = g + j + h;
                float tr = vr[b] * wr - vi[b] * wi;
                float ti = vr[b] * wi + vi[b] * wr;
                vr[b] = vr[a] - tr;  vi[b] = vi[a] - ti;
                vr[a] = vr[a] + tr;  vi[a] = vi[a] + ti;
            }
        }
    }
}

// One warp per 1024-pt inverse FFT: 1024 = 32 x 32 Cooley-Tukey.
// Round-5 proven launch config: 256 threads, 2 CTAs/SM, regs ~128, no spills.
__global__ __launch_bounds__(NT, 2) void ifft1024_warp(
    const float* __restrict__ re,
    const float* __restrict__ im,
    float* __restrict__ out_r,
    float* __restrict__ out_i)
{
    __shared__ float tbuf[WARPS][1024];   // 4KB per warp

    const int lane = threadIdx.x & 31;
    const int w    = threadIdx.x >> 5;
    const long long row = (long long)blockIdx.x * WARPS + w;

    const float* xr = re + row * NFFT;
    const float* xi = im + row * NFFT;

    float vr[32], vi[32];

    // Coalesced loads: lanes stride-1, 32 rows apart per register slot.
    #pragma unroll
    for (int n2 = 0; n2 < 32; n2++) {
        vr[n2] = xr[lane + 32 * n2];
        vi[n2] = xi[lane + 32 * n2];
    }

    // Step 1: A[lane, k2] = sum_{n2} W32^{n2 k2} x[lane + 32 n2]
    fft32_reg(vr, vi);

    // Step 2: multiply by inv * W1024^{lane * k2}, inv = 1/1024 folded into
    // the chain seeds (every element passes here exactly once).
    // 4 parallel chains of 8 dependent cmuls (serial depth /4).
    {
        const float inv = 1.0f / (float)NFFT;
        float s1, c1, s8, c8, s16, c16;
        sincospif((float)lane * (1.0f / 512.0f), &s1, &c1);    // w^1
        sincospif((float)lane * (1.0f / 64.0f),  &s8, &c8);    // w^8
        sincospif((float)lane * (1.0f / 32.0f),  &s16, &c16);  // w^16
        float c24 = c16 * c8 - s16 * s8;                       // w^24
        float s24 = c16 * s8 + s16 * c8;

        float cwr[4], cwi[4];
        cwr[0] = inv;        cwi[0] = 0.0f;
        cwr[1] = inv * c8;   cwi[1] = inv * s8;
        cwr[2] = inv * c16;  cwi[2] = inv * s16;
        cwr[3] = inv * c24;  cwi[3] = inv * s24;

        #pragma unroll
        for (int j = 0; j < 8; j++) {
            #pragma unroll
            for (int q = 0; q < 4; q++) {
                const int k = 8 * q + j;
                float br = vr[k] * cwr[q] - vi[k] * cwi[q];
                float bi = vr[k] * cwi[q] + vi[k] * cwr[q];
                vr[k] = br;  vi[k] = bi;
                float nr = cwr[q] * c1 - cwi[q] * s1;
                cwi[q]   = cwr[q] * s1 + cwi[q] * c1;
                cwr[q]   = nr;
            }
        }
    }

    // 32x32 transpose through warp-private shared, XOR-swizzled (conflict-free).
    float* buf = tbuf[w];
    #pragma unroll
    for (int k2 = 0; k2 < 32; k2++) buf[lane * 32 + (k2 ^ lane)] = vr[k2];
    __syncwarp();
    #pragma unroll
    for (int n1 = 0; n1 < 32; n1++) vr[n1] = buf[n1 * 32 + (lane ^ n1)];
    __syncwarp();
    #pragma unroll
    for (int k2 = 0; k2 < 32; k2++) buf[lane * 32 + (k2 ^ lane)] = vi[k2];
    __syncwarp();
    #pragma unroll
    for (int n1 = 0; n1 < 32; n1++) vi[n1] = buf[n1 * 32 + (lane ^ n1)];

    // Step 3: X[lane + 32 k1] = sum_{n1} W32^{n1 k1} B[n1, lane]
    fft32_reg(vr, vi);

    // Coalesced stores (scale already folded into step 2).
    float* orow  = out_r + row * NFFT;
    float* oirow = out_i + row * NFFT;
    #pragma unroll
    for (int k1 = 0; k1 < 32; k1++) {
        orow[lane + 32 * k1]  = vr[k1];
        oirow[lane + 32 * k1] = vi[k1];
    }
}

extern "C" void kernel_launch(void* const* d_in, const int* in_sizes, int n_in,
                              void* d_out, int out_size)
{
    const float* re = (const float*)d_in[0];
    const float* im = (const float*)d_in[1];
    float* out = (float*)d_out;

    const long long n_elems = (long long)in_sizes[0];   // 8*4096*1024
    const int nrows = (int)(n_elems / NFFT);            // 32768

    float* out_r = out;
    float* out_i = out + n_elems;                       // [yr | yi]

    ifft1024_warp<<<nrows / WARPS, NT>>>(re, im, out_r, out_i);
}